// round 4
// baseline (speedup 1.0000x reference)
#include <cuda_runtime.h>
#include <cuda_bf16.h>

#define BATCH 32
#define NAG   6
#define KS    256
#define QS    256
#define CHW   (512*32*32)       /* 524288 floats per (b,n) slab */
#define V4PB  (CHW/4)           /* 131072 float4 per (b,n) slab */

// Scratch (allocation-free rule: __device__ global)
__device__ float g_attn[BATCH * NAG];

// ---------------------------------------------------------------------------
// Kernel 1 (fully fused, reordered):
//   score[b,n] = sum_kk sum_d k[b,n,kk] W[kk,d] q[b,d]  +  sum_kk k[b,n,kk] b[kk]
// One block per batch, 256 threads. Thread t owns column d=t:
//   acc[n] = sum_kk k_s[n][kk] * W[kk,t]      (W coalesced, k smem-broadcast)
// then score[n] = block_reduce(acc[n] * q[t]) + biasdot[n]; sparsemax on t0.
// W is read once per block (32 blocks -> DRAM once, then L2 broadcast).
// ---------------------------------------------------------------------------
__global__ void __launch_bounds__(256)
attn_kernel(const float* __restrict__ q,
            const float* __restrict__ k,
            const float* __restrict__ W,
            const float* __restrict__ bias,
            float* __restrict__ out_attn,
            int write_attn) {
    const int b = blockIdx.x;
    const int t = threadIdx.x;
    const int wid = t >> 5, lane = t & 31;

    __shared__ float sk[NAG][KS];     // 6 KB
    __shared__ float sq[QS];          // 1 KB
    __shared__ float sbdot[NAG];
    __shared__ float sred[NAG][8];
    __shared__ float sscore[NAG];

    // stage q and the 6 k rows into smem
    sq[t] = q[(size_t)b * QS + t];
    #pragma unroll
    for (int n = 0; n < NAG; n++)
        sk[n][t] = k[(size_t)(b * NAG + n) * KS + t];
    __syncthreads();

    // bias-dot per agent: 6 warps, lane-strided over kk
    if (wid < NAG) {
        float s = 0.f;
        #pragma unroll
        for (int kk = lane; kk < KS; kk += 32)
            s = fmaf(sk[wid][kk], bias[kk], s);
        #pragma unroll
        for (int o = 16; o; o >>= 1) s += __shfl_xor_sync(0xffffffffu, s, o);
        if (lane == 0) sbdot[wid] = s;
    }

    // main loop: acc[n] += k[n][kk] * W[kk][t], unroll 8 for MLP
    float acc0 = 0.f, acc1 = 0.f, acc2 = 0.f, acc3 = 0.f, acc4 = 0.f, acc5 = 0.f;
    #pragma unroll 4
    for (int kk = 0; kk < KS; kk += 8) {
        float w[8];
        #pragma unroll
        for (int u = 0; u < 8; u++)
            w[u] = W[(size_t)(kk + u) * QS + t];     // coalesced across t
        #pragma unroll
        for (int u = 0; u < 8; u++) {
            const float* kc = &sk[0][kk + u];
            acc0 = fmaf(kc[0 * KS], w[u], acc0);
            acc1 = fmaf(kc[1 * KS], w[u], acc1);
            acc2 = fmaf(kc[2 * KS], w[u], acc2);
            acc3 = fmaf(kc[3 * KS], w[u], acc3);
            acc4 = fmaf(kc[4 * KS], w[u], acc4);
            acc5 = fmaf(kc[5 * KS], w[u], acc5);
        }
    }

    // multiply by q[t] and block-reduce each agent
    const float myq = sq[t];
    float vals[NAG] = { acc0 * myq, acc1 * myq, acc2 * myq,
                        acc3 * myq, acc4 * myq, acc5 * myq };
    #pragma unroll
    for (int n = 0; n < NAG; n++) {
        float s = vals[n];
        #pragma unroll
        for (int o = 16; o; o >>= 1) s += __shfl_xor_sync(0xffffffffu, s, o);
        if (lane == 0) sred[n][wid] = s;
    }
    __syncthreads();

    if (t < NAG) {
        float s = sbdot[t];
        #pragma unroll
        for (int w8 = 0; w8 < 8; w8++) s += sred[t][w8];
        sscore[t] = s;
    }
    __syncthreads();

    // sparsemax over 6 values on thread 0
    if (t == 0) {
        float z[NAG], zs[NAG];
        #pragma unroll
        for (int n = 0; n < NAG; n++) { z[n] = sscore[n]; zs[n] = z[n]; }
        #pragma unroll
        for (int i = 1; i < NAG; i++) {           // insertion sort, descending
            float key = zs[i]; int j = i - 1;
            while (j >= 0 && zs[j] < key) { zs[j + 1] = zs[j]; j--; }
            zs[j + 1] = key;
        }
        float cs[NAG], run = 0.f;
        #pragma unroll
        for (int r = 0; r < NAG; r++) { run += zs[r]; cs[r] = run; }
        int kk = 0;
        #pragma unroll
        for (int r = 1; r <= NAG; r++)
            if (1.0f + (float)r * zs[r - 1] > cs[r - 1]) kk++;
        const float tau = (cs[kk - 1] - 1.0f) / (float)kk;
        #pragma unroll
        for (int n = 0; n < NAG; n++) {
            float p = fmaxf(z[n] - tau, 0.0f);
            g_attn[b * NAG + n] = p;
            if (write_attn) out_attn[b * NAG + n] = p;
        }
    }
}

// ---------------------------------------------------------------------------
// Kernel 2: output[b,:] = sum_n attn[b,n] * v[b,n,:]
// Round-2 measured-best config: 4 float4 per thread, grid 4096, plain loads.
// Zero-weight agents skipped (block-uniform branch).
// ---------------------------------------------------------------------------
__global__ void __launch_bounds__(256)
wsum_kernel(const float* __restrict__ v, float* __restrict__ out) {
    const int b    = blockIdx.x >> 7;                       // 128 blocks/batch
    const int base = ((blockIdx.x & 127) << 10) + threadIdx.x;  // within slab

    __shared__ float sw[NAG];
    if (threadIdx.x < NAG) sw[threadIdx.x] = g_attn[b * NAG + threadIdx.x];
    __syncthreads();

    const float4* vb = (const float4*)v + (size_t)b * NAG * V4PB + base;

    float4 acc0 = make_float4(0.f, 0.f, 0.f, 0.f);
    float4 acc1 = acc0, acc2 = acc0, acc3 = acc0;

    #pragma unroll
    for (int n = 0; n < NAG; n++) {
        const float w = sw[n];
        if (w != 0.0f) {
            const float4* p = vb + (size_t)n * V4PB;
            float4 x0 = p[0];
            float4 x1 = p[256];
            float4 x2 = p[512];
            float4 x3 = p[768];
            acc0.x = fmaf(w, x0.x, acc0.x); acc0.y = fmaf(w, x0.y, acc0.y);
            acc0.z = fmaf(w, x0.z, acc0.z); acc0.w = fmaf(w, x0.w, acc0.w);
            acc1.x = fmaf(w, x1.x, acc1.x); acc1.y = fmaf(w, x1.y, acc1.y);
            acc1.z = fmaf(w, x1.z, acc1.z); acc1.w = fmaf(w, x1.w, acc1.w);
            acc2.x = fmaf(w, x2.x, acc2.x); acc2.y = fmaf(w, x2.y, acc2.y);
            acc2.z = fmaf(w, x2.z, acc2.z); acc2.w = fmaf(w, x2.w, acc2.w);
            acc3.x = fmaf(w, x3.x, acc3.x); acc3.y = fmaf(w, x3.y, acc3.y);
            acc3.z = fmaf(w, x3.z, acc3.z); acc3.w = fmaf(w, x3.w, acc3.w);
        }
    }

    float4* ob = (float4*)out + (size_t)b * V4PB + base;
    ob[0]   = acc0;
    ob[256] = acc1;
    ob[512] = acc2;
    ob[768] = acc3;
}

// ---------------------------------------------------------------------------
extern "C" void kernel_launch(void* const* d_in, const int* in_sizes, int n_in,
                              void* d_out, int out_size) {
    const float* q    = (const float*)d_in[0];
    const float* k    = (const float*)d_in[1];
    const float* v    = (const float*)d_in[2];
    const float* W    = (const float*)d_in[3];
    const float* bias = (const float*)d_in[4];

    float* out = (float*)d_out;
    const long long out_main = (long long)BATCH * CHW;        // 16777216
    const int write_attn = (out_size >= out_main + BATCH * NAG) ? 1 : 0;
    float* out_attn = out + out_main;

    attn_kernel<<<BATCH, 256>>>(q, k, W, bias, out_attn, write_attn);

    const int blocks = (BATCH * V4PB) / (256 * 4);            // 4096
    wsum_kernel<<<blocks, 256>>>(v, out);
}

// round 5
// speedup vs baseline: 1.6743x; 1.6743x over previous
#include <cuda_runtime.h>
#include <cuda_bf16.h>

#define BATCH 32
#define NAG   6
#define KS    256
#define QS    256
#define CHW   (512*32*32)       /* 524288 floats per (b,n) slab */
#define V4PB  (CHW/4)           /* 131072 float4 per (b,n) slab */
#define CHUNKS 8                /* kk-chunks per batch (32 rows each) */

// Scratch (allocation-free rule: __device__ globals). Zero-initialized at
// load; the finalizer block resets them so every graph replay starts clean.
__device__ float        g_attn[BATCH * NAG];
__device__ float        g_score[BATCH * NAG];
__device__ unsigned int g_cnt[BATCH];

// ---------------------------------------------------------------------------
// Kernel 1 (single-kernel attn): grid = 256 blocks (8 per batch), 256 thr.
// Block (b, c) computes query rows kk in [32c, 32c+32):
//     query[kk] = bias[kk] + W[kk,:] . q[b,:]        (warp-per-row dots)
// then partial scores s[n] = sum_{kk in chunk} k[b,n,kk] * query[kk]
// atomicAdd'ed into g_score. The 8th block per batch (ticket) runs sparsemax,
// writes g_attn / out_attn, and resets g_score / g_cnt.
// ---------------------------------------------------------------------------
__global__ void __launch_bounds__(256)
attn_kernel(const float* __restrict__ q,
            const float* __restrict__ k,
            const float* __restrict__ W,
            const float* __restrict__ bias,
            float* __restrict__ out_attn,
            int write_attn) {
    const int b      = blockIdx.x >> 3;
    const int kkbase = (blockIdx.x & 7) << 5;     // 32 rows per chunk
    const int t      = threadIdx.x;
    const int wid    = t >> 5, lane = t & 31;

    __shared__ float4 sq4[QS / 4];                // q[b] as 64 float4
    __shared__ float  squery[32];                 // this chunk's query rows
    __shared__ int    sflag;

    if (t < QS / 4) sq4[t] = ((const float4*)(q + (size_t)b * QS))[t];
    __syncthreads();

    // ---- phase A: warp `wid` computes 4 query rows (loads batched) ----
    {
        const int r0 = kkbase + (wid << 2);       // first of 4 rows
        float4 wv[8];
        #pragma unroll
        for (int r = 0; r < 4; r++) {
            const float4* wr = (const float4*)(W + (size_t)(r0 + r) * QS);
            wv[2 * r]     = wr[lane];
            wv[2 * r + 1] = wr[lane + 32];
        }
        const float4 q0 = sq4[lane], q1 = sq4[lane + 32];
        float s[4];
        #pragma unroll
        for (int r = 0; r < 4; r++) {
            float4 a = wv[2 * r], c = wv[2 * r + 1];
            s[r] = a.x * q0.x + a.y * q0.y + a.z * q0.z + a.w * q0.w
                 + c.x * q1.x + c.y * q1.y + c.z * q1.z + c.w * q1.w;
        }
        #pragma unroll
        for (int o = 16; o; o >>= 1) {
            #pragma unroll
            for (int r = 0; r < 4; r++)
                s[r] += __shfl_xor_sync(0xffffffffu, s[r], o);
        }
        if (lane == 0) {
            #pragma unroll
            for (int r = 0; r < 4; r++)
                squery[(wid << 2) + r] = s[r] + bias[r0 + r];
        }
    }
    __syncthreads();

    // ---- phase B: 6 warps -> partial scores for the 6 agents ----
    if (wid < NAG) {
        float p = k[(size_t)(b * NAG + wid) * KS + kkbase + lane] * squery[lane];
        #pragma unroll
        for (int o = 16; o; o >>= 1) p += __shfl_xor_sync(0xffffffffu, p, o);
        if (lane == 0) atomicAdd(&g_score[b * NAG + wid], p);
    }

    // ---- phase C: last block per batch finalizes ----
    __threadfence();
    if (t == 0) {
        unsigned tk = atomicAdd(&g_cnt[b], 1u);
        sflag = (tk == CHUNKS - 1);
    }
    __syncthreads();

    if (sflag && t == 0) {
        __threadfence();                          // acquire scores
        float z[NAG], zs[NAG];
        #pragma unroll
        for (int n = 0; n < NAG; n++) {
            z[n] = g_score[b * NAG + n];
            zs[n] = z[n];
            g_score[b * NAG + n] = 0.0f;          // reset for next replay
        }
        g_cnt[b] = 0u;
        #pragma unroll
        for (int i = 1; i < NAG; i++) {           // insertion sort, descending
            float key = zs[i]; int j = i - 1;
            while (j >= 0 && zs[j] < key) { zs[j + 1] = zs[j]; j--; }
            zs[j + 1] = key;
        }
        float cs[NAG], run = 0.f;
        #pragma unroll
        for (int r = 0; r < NAG; r++) { run += zs[r]; cs[r] = run; }
        int kk = 0;
        #pragma unroll
        for (int r = 1; r <= NAG; r++)
            if (1.0f + (float)r * zs[r - 1] > cs[r - 1]) kk++;
        const float tau = (cs[kk - 1] - 1.0f) / (float)kk;
        #pragma unroll
        for (int n = 0; n < NAG; n++) {
            float p = fmaxf(z[n] - tau, 0.0f);
            g_attn[b * NAG + n] = p;
            if (write_attn) out_attn[b * NAG + n] = p;
        }
        __threadfence();
    }
}

// ---------------------------------------------------------------------------
// Kernel 2: output[b,:] = sum_n attn[b,n] * v[b,n,:]
// Measured-best 4 float4/thread, grid 4096; min-blocks 6 to lift occupancy
// (was reg-limited at 44 regs -> 5 blocks/SM, occ 59%).
// ---------------------------------------------------------------------------
__global__ void __launch_bounds__(256, 6)
wsum_kernel(const float* __restrict__ v, float* __restrict__ out) {
    const int b    = blockIdx.x >> 7;                       // 128 blocks/batch
    const int base = ((blockIdx.x & 127) << 10) + threadIdx.x;  // within slab

    __shared__ float sw[NAG];
    if (threadIdx.x < NAG) sw[threadIdx.x] = g_attn[b * NAG + threadIdx.x];
    __syncthreads();

    const float4* vb = (const float4*)v + (size_t)b * NAG * V4PB + base;

    float4 acc0 = make_float4(0.f, 0.f, 0.f, 0.f);
    float4 acc1 = acc0, acc2 = acc0, acc3 = acc0;

    #pragma unroll
    for (int n = 0; n < NAG; n++) {
        const float w = sw[n];
        if (w != 0.0f) {
            const float4* p = vb + (size_t)n * V4PB;
            float4 x0 = p[0];
            float4 x1 = p[256];
            float4 x2 = p[512];
            float4 x3 = p[768];
            acc0.x = fmaf(w, x0.x, acc0.x); acc0.y = fmaf(w, x0.y, acc0.y);
            acc0.z = fmaf(w, x0.z, acc0.z); acc0.w = fmaf(w, x0.w, acc0.w);
            acc1.x = fmaf(w, x1.x, acc1.x); acc1.y = fmaf(w, x1.y, acc1.y);
            acc1.z = fmaf(w, x1.z, acc1.z); acc1.w = fmaf(w, x1.w, acc1.w);
            acc2.x = fmaf(w, x2.x, acc2.x); acc2.y = fmaf(w, x2.y, acc2.y);
            acc2.z = fmaf(w, x2.z, acc2.z); acc2.w = fmaf(w, x2.w, acc2.w);
            acc3.x = fmaf(w, x3.x, acc3.x); acc3.y = fmaf(w, x3.y, acc3.y);
            acc3.z = fmaf(w, x3.z, acc3.z); acc3.w = fmaf(w, x3.w, acc3.w);
        }
    }

    float4* ob = (float4*)out + (size_t)b * V4PB + base;
    ob[0]   = acc0;
    ob[256] = acc1;
    ob[512] = acc2;
    ob[768] = acc3;
}

// ---------------------------------------------------------------------------
extern "C" void kernel_launch(void* const* d_in, const int* in_sizes, int n_in,
                              void* d_out, int out_size) {
    const float* q    = (const float*)d_in[0];
    const float* k    = (const float*)d_in[1];
    const float* v    = (const float*)d_in[2];
    const float* W    = (const float*)d_in[3];
    const float* bias = (const float*)d_in[4];

    float* out = (float*)d_out;
    const long long out_main = (long long)BATCH * CHW;        // 16777216
    const int write_attn = (out_size >= out_main + BATCH * NAG) ? 1 : 0;
    float* out_attn = out + out_main;

    attn_kernel<<<BATCH * CHUNKS, 256>>>(q, k, W, bias, out_attn, write_attn);

    const int blocks = (BATCH * V4PB) / (256 * 4);            // 4096
    wsum_kernel<<<blocks, 256>>>(v, out);
}

// round 6
// speedup vs baseline: 1.7833x; 1.0651x over previous
#include <cuda_runtime.h>
#include <cuda_bf16.h>

#define BATCH 32
#define NAG   6
#define KS    256
#define QS    256
#define CHW   (512*32*32)       /* 524288 floats per (b,n) slab */
#define V4PB  (CHW/4)           /* 131072 float4 per (b,n) slab */
#define CHUNKS 8                /* attn kk-chunks per batch (32 rows each) */
#define WPB   128               /* wsum blocks per batch (grid 4096 / 32)  */
#define FLAGSTRIDE 32           /* pad flags to separate 128B lines */

// Scratch (allocation-free rule: __device__ globals). All counters/flags are
// reset within the kernel so every graph replay starts from the same state.
__device__ float                 g_attn[BATCH * NAG];
__device__ float                 g_score[BATCH * NAG];
__device__ unsigned int          g_cnt[BATCH];
__device__ unsigned int          g_done[BATCH];
__device__ volatile unsigned int g_flag[BATCH * FLAGSTRIDE];

// ---------------------------------------------------------------------------
// Single fused kernel, grid = 4096 x 256.
//  * blocks 0..255: attn chunk (b = bid>>3, rows [32c, 32c+32)):
//      query rows via warp dots -> partial agent scores -> atomicAdd;
//      ticketed finalizer does sparsemax, publishes g_attn, releases flag.
//  * all blocks: spin on their wsum batch's flag, then weighted sum
//      out[b,:] += attn[b,n] * v[b,n,:]   (zero-weight agents skipped).
//  * per-batch done counter resets flag/counters for the next graph replay.
// ---------------------------------------------------------------------------
__global__ void __launch_bounds__(256)
fused_kernel(const float* __restrict__ q,
             const float* __restrict__ k,
             const float* __restrict__ v,
             const float* __restrict__ W,
             const float* __restrict__ bias,
             float* __restrict__ out,
             float* __restrict__ out_attn,
             int write_attn) {
    const int bid  = blockIdx.x;
    const int t    = threadIdx.x;
    const int wid  = t >> 5, lane = t & 31;

    __shared__ float4 sq4[QS / 4];
    __shared__ float  squery[32];
    __shared__ float  sw[NAG];

    // ================= attn phase (blocks 0..255 only) ====================
    if (bid < BATCH * CHUNKS) {
        const int ab     = bid >> 3;
        const int kkbase = (bid & 7) << 5;

        if (t < QS / 4) sq4[t] = ((const float4*)(q + (size_t)ab * QS))[t];
        __syncthreads();

        // warp `wid` computes 4 query rows, 2 at a time (modest reg load)
        {
            const int r0 = kkbase + (wid << 2);
            const float4 q0 = sq4[lane], q1 = sq4[lane + 32];
            #pragma unroll
            for (int h = 0; h < 2; h++) {
                const int ra = r0 + 2 * h;
                const float4* wa = (const float4*)(W + (size_t)ra * QS);
                const float4* wb = (const float4*)(W + (size_t)(ra + 1) * QS);
                float4 a0 = wa[lane], a1 = wa[lane + 32];
                float4 b0 = wb[lane], b1 = wb[lane + 32];
                float sa = a0.x * q0.x + a0.y * q0.y + a0.z * q0.z + a0.w * q0.w
                         + a1.x * q1.x + a1.y * q1.y + a1.z * q1.z + a1.w * q1.w;
                float sb = b0.x * q0.x + b0.y * q0.y + b0.z * q0.z + b0.w * q0.w
                         + b1.x * q1.x + b1.y * q1.y + b1.z * q1.z + b1.w * q1.w;
                #pragma unroll
                for (int o = 16; o; o >>= 1) {
                    sa += __shfl_xor_sync(0xffffffffu, sa, o);
                    sb += __shfl_xor_sync(0xffffffffu, sb, o);
                }
                if (lane == 0) {
                    squery[(wid << 2) + 2 * h]     = sa + bias[ra];
                    squery[(wid << 2) + 2 * h + 1] = sb + bias[ra + 1];
                }
            }
        }
        __syncthreads();

        // 6 warps -> partial agent scores
        if (wid < NAG) {
            float p = k[(size_t)(ab * NAG + wid) * KS + kkbase + lane]
                    * squery[lane];
            #pragma unroll
            for (int o = 16; o; o >>= 1) p += __shfl_xor_sync(0xffffffffu, p, o);
            if (lane == 0) atomicAdd(&g_score[ab * NAG + wid], p);
        }

        __threadfence();
        if (t == 0 && atomicAdd(&g_cnt[ab], 1u) == CHUNKS - 1) {
            __threadfence();                      // acquire all partials
            float z[NAG], zs[NAG];
            #pragma unroll
            for (int n = 0; n < NAG; n++) {
                z[n] = g_score[ab * NAG + n];
                zs[n] = z[n];
                g_score[ab * NAG + n] = 0.0f;     // reset for next replay
            }
            g_cnt[ab] = 0u;
            #pragma unroll
            for (int i = 1; i < NAG; i++) {       // insertion sort, descending
                float key = zs[i]; int j = i - 1;
                while (j >= 0 && zs[j] < key) { zs[j + 1] = zs[j]; j--; }
                zs[j + 1] = key;
            }
            float cs[NAG], run = 0.f;
            #pragma unroll
            for (int r = 0; r < NAG; r++) { run += zs[r]; cs[r] = run; }
            int kk = 0;
            #pragma unroll
            for (int r = 1; r <= NAG; r++)
                if (1.0f + (float)r * zs[r - 1] > cs[r - 1]) kk++;
            const float tau = (cs[kk - 1] - 1.0f) / (float)kk;
            #pragma unroll
            for (int n = 0; n < NAG; n++) {
                float p = fmaxf(z[n] - tau, 0.0f);
                g_attn[ab * NAG + n] = p;
                if (write_attn) out_attn[ab * NAG + n] = p;
            }
            __threadfence();                      // publish before release
            g_flag[ab * FLAGSTRIDE] = 1u;
        }
        __syncthreads();
    }

    // ================= wsum phase (all 4096 blocks) ========================
    const int b    = bid >> 7;                          // 128 blocks/batch
    const int base = ((bid & 127) << 10) + t;           // within slab

    if (t == 0) {
        while (g_flag[b * FLAGSTRIDE] == 0u) __nanosleep(64);
    }
    __syncthreads();
    if (t < NAG) sw[t] = __ldcg(&g_attn[b * NAG + t]);
    __syncthreads();

    const float4* vb = (const float4*)v + (size_t)b * NAG * V4PB + base;

    float4 acc0 = make_float4(0.f, 0.f, 0.f, 0.f);
    float4 acc1 = acc0, acc2 = acc0, acc3 = acc0;

    #pragma unroll
    for (int n = 0; n < NAG; n++) {
        const float w = sw[n];
        if (w != 0.0f) {                   // block-uniform branch
            const float4* p = vb + (size_t)n * V4PB;
            float4 x0 = p[0];
            float4 x1 = p[256];
            float4 x2 = p[512];
            float4 x3 = p[768];
            acc0.x = fmaf(w, x0.x, acc0.x); acc0.y = fmaf(w, x0.y, acc0.y);
            acc0.z = fmaf(w, x0.z, acc0.z); acc0.w = fmaf(w, x0.w, acc0.w);
            acc1.x = fmaf(w, x1.x, acc1.x); acc1.y = fmaf(w, x1.y, acc1.y);
            acc1.z = fmaf(w, x1.z, acc1.z); acc1.w = fmaf(w, x1.w, acc1.w);
            acc2.x = fmaf(w, x2.x, acc2.x); acc2.y = fmaf(w, x2.y, acc2.y);
            acc2.z = fmaf(w, x2.z, acc2.z); acc2.w = fmaf(w, x2.w, acc2.w);
            acc3.x = fmaf(w, x3.x, acc3.x); acc3.y = fmaf(w, x3.y, acc3.y);
            acc3.z = fmaf(w, x3.z, acc3.z); acc3.w = fmaf(w, x3.w, acc3.w);
        }
    }

    float4* ob = (float4*)out + (size_t)b * V4PB + base;
    ob[0]   = acc0;
    ob[256] = acc1;
    ob[512] = acc2;
    ob[768] = acc3;

    // -------- per-batch cleanup so the next graph replay starts clean ------
    __syncthreads();
    if (t == 0 && atomicAdd(&g_done[b], 1u) == WPB - 1) {
        g_done[b] = 0u;
        g_flag[b * FLAGSTRIDE] = 0u;
    }
}

// ---------------------------------------------------------------------------
extern "C" void kernel_launch(void* const* d_in, const int* in_sizes, int n_in,
                              void* d_out, int out_size) {
    const float* q    = (const float*)d_in[0];
    const float* k    = (const float*)d_in[1];
    const float* v    = (const float*)d_in[2];
    const float* W    = (const float*)d_in[3];
    const float* bias = (const float*)d_in[4];

    float* out = (float*)d_out;
    const long long out_main = (long long)BATCH * CHW;        // 16777216
    const int write_attn = (out_size >= out_main + BATCH * NAG) ? 1 : 0;
    float* out_attn = out + out_main;

    const int blocks = (BATCH * V4PB) / (256 * 4);            // 4096
    fused_kernel<<<blocks, 256>>>(q, k, v, W, bias, out, out_attn, write_attn);
}

// round 7
// speedup vs baseline: 1.9243x; 1.0790x over previous
#include <cuda_runtime.h>
#include <cuda_bf16.h>

#define BATCH 32
#define NAG   6
#define KS    256
#define QS    256
#define CHW   (512*32*32)       /* 524288 floats per (b,n) slab */
#define V4PB  (CHW/4)           /* 131072 float4 per (b,n) slab */
#define CHUNKS 8                /* attn kk-chunks per batch (32 rows each) */
#define WPB   128               /* wsum blocks per batch (grid 4096 / 32)  */
#define FLAGSTRIDE 32           /* pad flags to separate 128B lines */

// Scratch (allocation-free rule: __device__ globals). All counters/flags are
// reset within the kernel so every graph replay starts from the same state.
__device__ float                 g_attn[BATCH * NAG];
__device__ float                 g_score[BATCH * NAG];
__device__ unsigned int          g_cnt[BATCH];
__device__ unsigned int          g_done[BATCH];
__device__ volatile unsigned int g_flag[BATCH * FLAGSTRIDE];

// ---------------------------------------------------------------------------
// Single fused kernel, grid = 4096 x 256.
//  * blocks 0..255: attn chunk -> partial scores -> ticketed sparsemax ->
//    publish g_attn, release per-batch flag.
//  * all blocks: spin on flag, then out[b,:] = sum_n attn[b,n] * v[b,n,:]
//    (zero-weight agents skipped; branch is block-uniform).
//  * per-batch done counter resets flags/counters for the next graph replay.
// All wsum-phase indexing is 32-bit to keep register count at the measured
// sweet spot (~44 regs -> 5-6 blocks/SM).
// ---------------------------------------------------------------------------
__global__ void __launch_bounds__(256)
fused_kernel(const float* __restrict__ q,
             const float* __restrict__ k,
             const float* __restrict__ v,
             const float* __restrict__ W,
             const float* __restrict__ bias,
             float* __restrict__ out,
             float* __restrict__ out_attn,
             int write_attn) {
    const int bid  = blockIdx.x;
    const int t    = threadIdx.x;
    const int wid  = t >> 5, lane = t & 31;

    __shared__ float4 sq4[QS / 4];
    __shared__ float  squery[32];
    __shared__ float  sw[NAG];

    // ================= attn phase (blocks 0..255 only) ====================
    if (bid < BATCH * CHUNKS) {
        const int ab     = bid >> 3;
        const int kkbase = (bid & 7) << 5;

        if (t < QS / 4) sq4[t] = ((const float4*)(q + ab * QS))[t];
        __syncthreads();

        // warp `wid` computes 4 query rows, 2 at a time (modest reg load)
        {
            const int r0 = kkbase + (wid << 2);
            const float4 q0 = sq4[lane], q1 = sq4[lane + 32];
            #pragma unroll
            for (int h = 0; h < 2; h++) {
                const int ra = r0 + 2 * h;
                const float4* wa = (const float4*)(W + ra * QS);
                const float4* wb = (const float4*)(W + (ra + 1) * QS);
                float4 a0 = wa[lane], a1 = wa[lane + 32];
                float4 b0 = wb[lane], b1 = wb[lane + 32];
                float sa = a0.x * q0.x + a0.y * q0.y + a0.z * q0.z + a0.w * q0.w
                         + a1.x * q1.x + a1.y * q1.y + a1.z * q1.z + a1.w * q1.w;
                float sb = b0.x * q0.x + b0.y * q0.y + b0.z * q0.z + b0.w * q0.w
                         + b1.x * q1.x + b1.y * q1.y + b1.z * q1.z + b1.w * q1.w;
                #pragma unroll
                for (int o = 16; o; o >>= 1) {
                    sa += __shfl_xor_sync(0xffffffffu, sa, o);
                    sb += __shfl_xor_sync(0xffffffffu, sb, o);
                }
                if (lane == 0) {
                    squery[(wid << 2) + 2 * h]     = sa + bias[ra];
                    squery[(wid << 2) + 2 * h + 1] = sb + bias[ra + 1];
                }
            }
        }
        __syncthreads();

        // 6 warps -> partial agent scores
        if (wid < NAG) {
            float p = k[(ab * NAG + wid) * KS + kkbase + lane] * squery[lane];
            #pragma unroll
            for (int o = 16; o; o >>= 1) p += __shfl_xor_sync(0xffffffffu, p, o);
            if (lane == 0) atomicAdd(&g_score[ab * NAG + wid], p);
        }

        __threadfence();
        if (t == 0 && atomicAdd(&g_cnt[ab], 1u) == CHUNKS - 1) {
            __threadfence();                      // acquire all partials
            float z[NAG], zs[NAG];
            #pragma unroll
            for (int n = 0; n < NAG; n++) {
                z[n] = g_score[ab * NAG + n];
                zs[n] = z[n];
                g_score[ab * NAG + n] = 0.0f;     // reset for next replay
            }
            g_cnt[ab] = 0u;
            #pragma unroll
            for (int i = 1; i < NAG; i++) {       // insertion sort, descending
                float key = zs[i]; int j = i - 1;
                while (j >= 0 && zs[j] < key) { zs[j + 1] = zs[j]; j--; }
                zs[j + 1] = key;
            }
            float cs[NAG], run = 0.f;
            #pragma unroll
            for (int r = 0; r < NAG; r++) { run += zs[r]; cs[r] = run; }
            int kk = 0;
            #pragma unroll
            for (int r = 1; r <= NAG; r++)
                if (1.0f + (float)r * zs[r - 1] > cs[r - 1]) kk++;
            const float tau = (cs[kk - 1] - 1.0f) / (float)kk;
            #pragma unroll
            for (int n = 0; n < NAG; n++) {
                float p = fmaxf(z[n] - tau, 0.0f);
                g_attn[ab * NAG + n] = p;
                if (write_attn) out_attn[ab * NAG + n] = p;
            }
            __threadfence();                      // publish before release
            g_flag[ab * FLAGSTRIDE] = 1u;
        }
        __syncthreads();
    }

    // ================= wsum phase (all 4096 blocks) ========================
    const int b    = bid >> 7;                          // 128 blocks/batch
    const int base = ((bid & 127) << 10) + t;           // float4 idx in slab

    if (t == 0) {
        while (g_flag[b * FLAGSTRIDE] == 0u) __nanosleep(64);
    }
    __syncthreads();
    if (t < NAG) sw[t] = __ldcg(&g_attn[b * NAG + t]);
    __syncthreads();

    // 32-bit offsets: b*(NAG*V4PB)+base <= 25.2M, fits easily.
    const float4* vb = (const float4*)v + (b * (NAG * V4PB) + base);

    float4 acc0 = make_float4(0.f, 0.f, 0.f, 0.f);
    float4 acc1 = acc0, acc2 = acc0, acc3 = acc0;

    #pragma unroll
    for (int n = 0; n < NAG; n++) {
        const float w = sw[n];
        if (w != 0.0f) {                   // block-uniform branch
            const float4* p = vb + n * V4PB;
            float4 x0 = __ldcs(p);
            float4 x1 = __ldcs(p + 256);
            float4 x2 = __ldcs(p + 512);
            float4 x3 = __ldcs(p + 768);
            acc0.x = fmaf(w, x0.x, acc0.x); acc0.y = fmaf(w, x0.y, acc0.y);
            acc0.z = fmaf(w, x0.z, acc0.z); acc0.w = fmaf(w, x0.w, acc0.w);
            acc1.x = fmaf(w, x1.x, acc1.x); acc1.y = fmaf(w, x1.y, acc1.y);
            acc1.z = fmaf(w, x1.z, acc1.z); acc1.w = fmaf(w, x1.w, acc1.w);
            acc2.x = fmaf(w, x2.x, acc2.x); acc2.y = fmaf(w, x2.y, acc2.y);
            acc2.z = fmaf(w, x2.z, acc2.z); acc2.w = fmaf(w, x2.w, acc2.w);
            acc3.x = fmaf(w, x3.x, acc3.x); acc3.y = fmaf(w, x3.y, acc3.y);
            acc3.z = fmaf(w, x3.z, acc3.z); acc3.w = fmaf(w, x3.w, acc3.w);
        }
    }

    float4* ob = (float4*)out + (b * V4PB + base);
    __stcs(ob,       acc0);
    __stcs(ob + 256, acc1);
    __stcs(ob + 512, acc2);
    __stcs(ob + 768, acc3);

    // -------- per-batch cleanup so the next graph replay starts clean ------
    __syncthreads();
    if (t == 0 && atomicAdd(&g_done[b], 1u) == WPB - 1) {
        g_done[b] = 0u;
        g_flag[b * FLAGSTRIDE] = 0u;
    }
}

// ---------------------------------------------------------------------------
extern "C" void kernel_launch(void* const* d_in, const int* in_sizes, int n_in,
                              void* d_out, int out_size) {
    const float* q    = (const float*)d_in[0];
    const float* k    = (const float*)d_in[1];
    const float* v    = (const float*)d_in[2];
    const float* W    = (const float*)d_in[3];
    const float* bias = (const float*)d_in[4];

    float* out = (float*)d_out;
    const long long out_main = (long long)BATCH * CHW;        // 16777216
    const int write_attn = (out_size >= out_main + BATCH * NAG) ? 1 : 0;
    float* out_attn = out + out_main;

    const int blocks = (BATCH * V4PB) / (256 * 4);            // 4096
    fused_kernel<<<blocks, 256>>>(q, k, v, W, bias, out, out_attn, write_attn);
}